// round 1
// baseline (speedup 1.0000x reference)
#include <cuda_runtime.h>
#include <cstdint>
#include <math.h>

// Problem constants
#define BK  8
#define CK  32
#define KK  512
#define ROWS 8
#define TPB 512

// ---------------------------------------------------------------------------
// JAX threefry2x32 with key = (0, 42)  (jax.random.key(42) -> [0, 42])
// Random123 Threefry-2x32-20, rotation sets (13,15,26,6) / (17,29,16,24).
// ---------------------------------------------------------------------------
__device__ __forceinline__ void threefry2x32_k42(uint32_t x0, uint32_t x1,
                                                 uint32_t& o0, uint32_t& o1) {
    const uint32_t ks0 = 0u;
    const uint32_t ks1 = 42u;
    const uint32_t ks2 = 0x1BD11BDAu ^ 0u ^ 42u;
    x0 += ks0; x1 += ks1;
#define TF_R(r) { x0 += x1; x1 = (x1 << (r)) | (x1 >> (32 - (r))); x1 ^= x0; }
    TF_R(13) TF_R(15) TF_R(26) TF_R(6)
    x0 += ks1; x1 += ks2 + 1u;
    TF_R(17) TF_R(29) TF_R(16) TF_R(24)
    x0 += ks2; x1 += ks0 + 2u;
    TF_R(13) TF_R(15) TF_R(26) TF_R(6)
    x0 += ks0; x1 += ks1 + 3u;
    TF_R(17) TF_R(29) TF_R(16) TF_R(24)
    x0 += ks1; x1 += ks2 + 4u;
    TF_R(13) TF_R(15) TF_R(26) TF_R(6)
    x0 += ks2; x1 += ks0 + 5u;
#undef TF_R
    o0 = x0; o1 = x1;
}

// Partitionable threefry random bits (JAX default): counter = 64-bit flat index,
// split into (hi, lo) 32-bit halves; 32-bit output = o0 ^ o1.
// Here total size = 4,194,304 < 2^32 so hi is always 0.
__device__ __forceinline__ uint32_t jax_random_bits32(uint32_t e) {
    uint32_t a, b;
    threefry2x32_k42(0u, e, a, b);
    return a ^ b;
}

// jax.random.uniform bit->float conversion, minval=1e-10, maxval=1.0 (f32):
// f = bitcast((bits >> 9) | 0x3f800000) - 1.0 in [0,1)
// u = max(1e-10, f * (1.0 - 1e-10) + 1e-10); (1.0 - 1e-10) rounds to 1.0f.
__device__ __forceinline__ float jax_uniform(uint32_t bits) {
    float f = __uint_as_float((bits >> 9) | 0x3f800000u) - 1.0f;
    return fmaxf(1e-10f, f + 1e-10f);
}

// ---------------------------------------------------------------------------
// Kernels
// ---------------------------------------------------------------------------
__global__ void zero_out_kernel(float* __restrict__ out) {
    out[blockIdx.x * TPB + threadIdx.x] = 0.0f;
}

__global__ void __launch_bounds__(TPB, 1)
dist_sample_kernel(const float* __restrict__ amp,
                   const float* __restrict__ ph,
                   const float* __restrict__ Amat,
                   const float* __restrict__ wamp_p,
                   const float* __restrict__ wph_p,
                   float* __restrict__ out) {
    extern __shared__ float sm[];
    float* sA = sm;             // [CK][KK] amplitude slice for this b
    float* sP = sm + CK * KK;   // [CK][KK] phase slice for this b
    __shared__ float red[18];

    const int b = blockIdx.y;
    const int j = threadIdx.x;
    const int wid = j >> 5;
    const int lane = j & 31;

    const float wa = wamp_p[0];
    const float wp = wph_p[0];

    // Cooperative load of this batch's (C,K) slices into shared memory.
    const float* ab = amp + (size_t)b * CK * KK;
    const float* pb = ph + (size_t)b * CK * KK;
    for (int t = threadIdx.x; t < CK * KK; t += TPB) {
        sA[t] = ab[t];
        sP[t] = pb[t];
    }
    // diag(A) element for this thread's column j
    const float dj = Amat[(size_t)j * KK + j];
    __syncthreads();

    for (int r = 0; r < ROWS; r++) {
        const int i = blockIdx.x * ROWS + r;

        // dist[b,i,j] = sum_c ( (wa*(a_i-a_j) + wp*(p_i-p_j)) * A[j,j] )^2
        float acc = 0.0f;
#pragma unroll
        for (int c = 0; c < CK; c++) {
            float ad = sA[c * KK + i] - sA[c * KK + j];
            float pd = sP[c * KK + i] - sP[c * KK + j];
            float f  = wa * ad + wp * pd;
            float t  = f * dj;
            acc = fmaf(t, t, acc);
        }

        // exp_dist with zeroed diagonal
        float e = (j == i) ? 0.0f : 1.0f / (acc + 1e-10f);

        // Block-wide max over j (row max)
        float v = e;
#pragma unroll
        for (int o = 16; o; o >>= 1)
            v = fmaxf(v, __shfl_xor_sync(0xffffffffu, v, o));
        __syncthreads();                 // prior-row red[] reads are done
        if (lane == 0) red[wid] = v;
        __syncthreads();
        if (wid == 0) {
            float t = red[lane & 15];
#pragma unroll
            for (int o = 8; o; o >>= 1)
                t = fmaxf(t, __shfl_xor_sync(0xffffffffu, t, o));
            if (lane == 0) red[16] = t;
        }
        __syncthreads();
        const float emax = red[16];

        // p = ((e/emax)*offdiag + eye) * 0.99
        float p = (j == i) ? 0.99f : (e / emax) * 0.99f;
        float logit = logf(p / (1.0f - p));

        // gumbel-softmax hard sample: index 0 wins iff logit+g0 >= -logit+g1
        uint32_t m  = ((uint32_t)(b * KK + i)) * (uint32_t)KK + (uint32_t)j;
        uint32_t b0 = jax_random_bits32(2u * m);
        uint32_t b1 = jax_random_bits32(2u * m + 1u);
        float u0 = jax_uniform(b0);
        float u1 = jax_uniform(b1);
        float g0 = -logf(-logf(u0));
        float g1 = -logf(-logf(u1));

        if (logit + g0 >= g1 - logit)
            atomicAdd(&out[(size_t)i * KK + j], 0.125f);   // mean over B=8, exact in fp
    }
}

// ---------------------------------------------------------------------------
// Launch
// ---------------------------------------------------------------------------
extern "C" void kernel_launch(void* const* d_in, const int* in_sizes, int n_in,
                              void* d_out, int out_size) {
    const float* amp = (const float*)d_in[0];
    const float* ph  = (const float*)d_in[1];
    const float* A   = (const float*)d_in[2];
    const float* wa  = (const float*)d_in[3];
    const float* wp  = (const float*)d_in[4];
    float* out = (float*)d_out;

    const int smem_bytes = 2 * CK * KK * (int)sizeof(float);   // 128 KB
    cudaFuncSetAttribute(dist_sample_kernel,
                         cudaFuncAttributeMaxDynamicSharedMemorySize, smem_bytes);

    zero_out_kernel<<<(KK * KK) / TPB, TPB>>>(out);
    dist_sample_kernel<<<dim3(KK / ROWS, BK), TPB, smem_bytes>>>(
        amp, ph, A, wa, wp, out);
}

// round 3
// speedup vs baseline: 1.5765x; 1.5765x over previous
#include <cuda_runtime.h>
#include <cstdint>
#include <math.h>

// Problem constants
#define BK  8
#define CK  32
#define KK  512
#define ROWS 8
#define TPB 512

// ---------------------------------------------------------------------------
// JAX threefry2x32 with key = (0, 42)  (jax.random.key(42) -> [0, 42])
// Random123 Threefry-2x32-20, rotation sets (13,15,26,6) / (17,29,16,24).
// ---------------------------------------------------------------------------
__device__ __forceinline__ void threefry2x32_k42(uint32_t x0, uint32_t x1,
                                                 uint32_t& o0, uint32_t& o1) {
    const uint32_t ks0 = 0u;
    const uint32_t ks1 = 42u;
    const uint32_t ks2 = 0x1BD11BDAu ^ 0u ^ 42u;
    x0 += ks0; x1 += ks1;
#define TF_R(r) { x0 += x1; x1 = (x1 << (r)) | (x1 >> (32 - (r))); x1 ^= x0; }
    TF_R(13) TF_R(15) TF_R(26) TF_R(6)
    x0 += ks1; x1 += ks2 + 1u;
    TF_R(17) TF_R(29) TF_R(16) TF_R(24)
    x0 += ks2; x1 += ks0 + 2u;
    TF_R(13) TF_R(15) TF_R(26) TF_R(6)
    x0 += ks0; x1 += ks1 + 3u;
    TF_R(17) TF_R(29) TF_R(16) TF_R(24)
    x0 += ks1; x1 += ks2 + 4u;
    TF_R(13) TF_R(15) TF_R(26) TF_R(6)
    x0 += ks2; x1 += ks0 + 5u;
#undef TF_R
    o0 = x0; o1 = x1;
}

__device__ __forceinline__ uint32_t jax_random_bits32(uint32_t e) {
    uint32_t a, b;
    threefry2x32_k42(0u, e, a, b);
    return a ^ b;
}

// jax.random.uniform bit->float, minval=1e-10, maxval=1.0 (f32)
__device__ __forceinline__ float jax_uniform(uint32_t bits) {
    float f = __uint_as_float((bits >> 9) | 0x3f800000u) - 1.0f;
    return fmaxf(1e-10f, f + 1e-10f);
}

// ---------------------------------------------------------------------------
// Kernels
// ---------------------------------------------------------------------------
__global__ void zero_out_kernel(float* __restrict__ out) {
    out[blockIdx.x * TPB + threadIdx.x] = 0.0f;
}

__global__ void __launch_bounds__(TPB, 2)
dist_sample_kernel(const float* __restrict__ amp,
                   const float* __restrict__ ph,
                   const float* __restrict__ Amat,
                   const float* __restrict__ wamp_p,
                   const float* __restrict__ wph_p,
                   float* __restrict__ out) {
    __shared__ float sQi[ROWS][CK];      // fused rows for this block
    __shared__ float sRed[16][ROWS];     // per-warp row maxima
    __shared__ float sC[ROWS];           // 0.99 / emax per row

    const int b    = blockIdx.y;
    const int j    = threadIdx.x;
    const int wid  = j >> 5;
    const int lane = j & 31;
    const int i0   = blockIdx.x * ROWS;

    const float wa = wamp_p[0];
    const float wp = wph_p[0];

    const float* ab = amp + (size_t)b * CK * KK;
    const float* pb = ph  + (size_t)b * CK * KK;

    // Per-thread column cache: q[c] = wa*a[c][j] + wp*p[c][j]  (coalesced LDG)
    float qj[CK];
#pragma unroll
    for (int c = 0; c < CK; c++)
        qj[c] = wa * ab[c * KK + j] + wp * pb[c * KK + j];

    // Block's 8 row vectors into smem (256 threads participate)
    if (j < ROWS * CK) {
        int r = j >> 5, c = j & 31;
        int i = i0 + r;
        sQi[r][c] = wa * ab[c * KK + i] + wp * pb[c * KK + i];
    }

    const float dj   = Amat[(size_t)j * KK + j];
    const float djsq = dj * dj;
    __syncthreads();

    // Phase A: e[r] = offdiag / (djsq * sum_c (qi - qj)^2 + 1e-10)
    float e[ROWS];
#pragma unroll
    for (int r = 0; r < ROWS; r++) {
        float acc = 0.0f;
        const float2* q2 = (const float2*)sQi[r];
#pragma unroll
        for (int c2 = 0; c2 < CK / 2; c2++) {
            float2 qi = q2[c2];                         // broadcast LDS.64
            float d0 = qi.x - qj[2 * c2];
            acc = fmaf(d0, d0, acc);
            float d1 = qi.y - qj[2 * c2 + 1];
            acc = fmaf(d1, d1, acc);
        }
        e[r] = (i0 + r == j) ? 0.0f : 1.0f / fmaf(acc, djsq, 1e-10f);
    }

    // Phase B: row maxima, all 8 rows with 2 barriers total
#pragma unroll
    for (int r = 0; r < ROWS; r++) {
        float v = e[r];
#pragma unroll
        for (int o = 16; o; o >>= 1)
            v = fmaxf(v, __shfl_xor_sync(0xffffffffu, v, o));
        if (lane == 0) sRed[wid][r] = v;
    }
    __syncthreads();
    if (wid < ROWS) {                    // warp w reduces row w across 16 warps
        float v = (lane < 16) ? sRed[lane][wid] : 0.0f;
#pragma unroll
        for (int o = 8; o; o >>= 1)
            v = fmaxf(v, __shfl_xor_sync(0xffffffffu, v, o));
        if (lane == 0) sC[wid] = 0.99f / v;
    }
    __syncthreads();

    // Phase C: bernoulli gumbel hard sample.
    // Decision logit+g0 >= -logit+g1  <=>  p^2 * L1 >= (1-p)^2 * L0,
    // with L = -log(u) and p in (0, 0.99].
#pragma unroll
    for (int r = 0; r < ROWS; r++) {
        const int i = i0 + r;
        float p  = (i == j) ? 0.99f : e[r] * sC[r];
        float om = 1.0f - p;

        uint32_t m  = ((uint32_t)(b * KK + i)) * (uint32_t)KK + (uint32_t)j;
        float u0 = jax_uniform(jax_random_bits32(2u * m));
        float u1 = jax_uniform(jax_random_bits32(2u * m + 1u));
        float L0 = -__logf(u0);
        float L1 = -__logf(u1);

        if (p * p * L1 >= om * om * L0)
            atomicAdd(&out[(size_t)i * KK + j], 0.125f);  // mean over B=8, exact
    }
}

// ---------------------------------------------------------------------------
// Launch
// ---------------------------------------------------------------------------
extern "C" void kernel_launch(void* const* d_in, const int* in_sizes, int n_in,
                              void* d_out, int out_size) {
    const float* amp = (const float*)d_in[0];
    const float* ph  = (const float*)d_in[1];
    const float* A   = (const float*)d_in[2];
    const float* wa  = (const float*)d_in[3];
    const float* wp  = (const float*)d_in[4];
    float* out = (float*)d_out;

    zero_out_kernel<<<(KK * KK) / TPB, TPB>>>(out);
    dist_sample_kernel<<<dim3(KK / ROWS, BK), TPB>>>(amp, ph, A, wa, wp, out);
}

// round 4
// speedup vs baseline: 2.7093x; 1.7185x over previous
#include <cuda_runtime.h>
#include <cstdint>
#include <math.h>
#include <float.h>

// Problem constants
#define BK  8
#define CK  32
#define KK  512
#define ROWS 8
#define TPB 512

// ---------------------------------------------------------------------------
// JAX threefry2x32 with key = (0, 42).  Random123 Threefry-2x32-20.
// The x0-accumulate of each round is issued as IMAD (x0 = x1*one + x0) with
// `one` an opaque runtime value, moving 20 adds/call from the ALU pipe to the
// FMA pipe. Rotates forced to single SHF.L.W via __funnelshift_l.
// ---------------------------------------------------------------------------
__device__ __forceinline__ void threefry2x32_k42(uint32_t x0, uint32_t x1,
                                                 uint32_t one,
                                                 uint32_t& o0, uint32_t& o1) {
    const uint32_t ks1 = 42u;
    const uint32_t ks2 = 0x1BD11BDAu ^ 42u;
    /* x0 += 0 */ x1 += ks1;
#define TF_R(r) {                                                         \
    asm("mad.lo.s32 %0, %1, %2, %0;" : "+r"(x0) : "r"(x1), "r"(one));     \
    x1 = __funnelshift_l(x1, x1, (r));                                    \
    x1 ^= x0; }
    TF_R(13) TF_R(15) TF_R(26) TF_R(6)
    x0 += ks1; x1 += ks2 + 1u;
    TF_R(17) TF_R(29) TF_R(16) TF_R(24)
    x0 += ks2; x1 += 0u + 2u;
    TF_R(13) TF_R(15) TF_R(26) TF_R(6)
    x0 += 0u;  x1 += ks1 + 3u;
    TF_R(17) TF_R(29) TF_R(16) TF_R(24)
    x0 += ks1; x1 += ks2 + 4u;
    TF_R(13) TF_R(15) TF_R(26) TF_R(6)
    x0 += ks2; x1 += 0u + 5u;
#undef TF_R
    o0 = x0; o1 = x1;
}

__device__ __forceinline__ uint32_t jax_random_bits32(uint32_t e, uint32_t one) {
    uint32_t a, b;
    threefry2x32_k42(0u, e, one, a, b);
    return a ^ b;
}

// jax.random.uniform bit->float, minval=1e-10, maxval=1.0 (f32)
__device__ __forceinline__ float jax_uniform(uint32_t bits) {
    float f = __uint_as_float((bits >> 9) | 0x3f800000u) - 1.0f;
    return fmaxf(1e-10f, f + 1e-10f);
}

// ---------------------------------------------------------------------------
// Kernels
// ---------------------------------------------------------------------------
__global__ void zero_out_kernel(float* __restrict__ out) {
    out[blockIdx.x * TPB + threadIdx.x] = 0.0f;
}

__global__ void __launch_bounds__(TPB, 2)
dist_sample_kernel(const float* __restrict__ amp,
                   const float* __restrict__ ph,
                   const float* __restrict__ Amat,
                   const float* __restrict__ wamp_p,
                   const float* __restrict__ wph_p,
                   float* __restrict__ out,
                   uint32_t one) {
    __shared__ float sQi[ROWS][CK];      // fused row vectors q_i
    __shared__ float sSi[ROWS];          // sum_c q_i[c]^2 per row
    __shared__ float sRed[16][ROWS];     // per-warp row minima of D
    __shared__ float sC[ROWS];           // 0.99 * Dmin per row

    const int b    = blockIdx.y;
    const int j    = threadIdx.x;
    const int wid  = j >> 5;
    const int lane = j & 31;
    const int i0   = blockIdx.x * ROWS;

    const float wa = wamp_p[0];
    const float wp = wph_p[0];

    const float* ab = amp + (size_t)b * CK * KK;
    const float* pb = ph  + (size_t)b * CK * KK;

    // Per-thread column cache q_j[c] = wa*a + wp*p, and its sum of squares.
    float qj[CK];
    float Sj = 0.0f;
#pragma unroll
    for (int c = 0; c < CK; c++) {
        float v = wa * ab[c * KK + j] + wp * pb[c * KK + j];
        qj[c] = v;
        Sj = fmaf(v, v, Sj);
    }

    // Block's 8 row vectors + their sums of squares (warps 0..7, lane = c)
    if (wid < ROWS) {
        const int i = i0 + wid;
        float v = wa * ab[lane * KK + i] + wp * pb[lane * KK + i];
        sQi[wid][lane] = v;
        float s = v * v;
#pragma unroll
        for (int o = 16; o; o >>= 1)
            s += __shfl_xor_sync(0xffffffffu, s, o);
        if (lane == 0) sSi[wid] = s;
    }

    const float dj   = Amat[(size_t)j * KK + j];
    const float djsq = dj * dj;
    __syncthreads();

    // Phase A: D = djsq * ||q_i - q_j||^2 + 1e-10 via expanded dot product.
    float D[ROWS];
#pragma unroll
    for (int r = 0; r < ROWS; r++) {
        float dot = 0.0f;
        const float2* q2 = (const float2*)sQi[r];
#pragma unroll
        for (int c2 = 0; c2 < CK / 2; c2++) {
            float2 qi = q2[c2];                       // broadcast LDS.64
            dot = fmaf(qi.x, qj[2 * c2], dot);
            dot = fmaf(qi.y, qj[2 * c2 + 1], dot);
        }
        float ss = fmaxf(fmaf(dot, -2.0f, sSi[r] + Sj), 0.0f);
        D[r] = (i0 + r == j) ? FLT_MAX : fmaf(ss, djsq, 1e-10f);
    }

    // Phase B: row minima of D (diagonal excluded via FLT_MAX)
#pragma unroll
    for (int r = 0; r < ROWS; r++) {
        float v = D[r];
#pragma unroll
        for (int o = 16; o; o >>= 1)
            v = fminf(v, __shfl_xor_sync(0xffffffffu, v, o));
        if (lane == 0) sRed[wid][r] = v;
    }
    __syncthreads();
    if (wid < ROWS) {                    // warp w reduces row w across 16 warps
        float v = (lane < 16) ? sRed[lane][wid] : FLT_MAX;
#pragma unroll
        for (int o = 8; o; o >>= 1)
            v = fminf(v, __shfl_xor_sync(0xffffffffu, v, o));
        if (lane == 0) sC[wid] = 0.99f * v;
    }
    __syncthreads();

    // Phase C: bernoulli gumbel hard sample, division-free.
    // p = 0.99*Dmin/D; decide logit+g0 >= -logit+g1  <=>  p^2 L1 >= (1-p)^2 L0
    //  <=> (0.99*Dmin)^2 * L1 >= (D - 0.99*Dmin)^2 * L0   (multiply by D^2).
#pragma unroll
    for (int r = 0; r < ROWS; r++) {
        const int i = i0 + r;
        const bool diag = (i == j);
        float a  = diag ? 0.99f : sC[r];
        float bb = diag ? 0.01f : D[r] - sC[r];

        uint32_t m  = ((uint32_t)(b * KK + i)) * (uint32_t)KK + (uint32_t)j;
        float u0 = jax_uniform(jax_random_bits32(2u * m, one));
        float u1 = jax_uniform(jax_random_bits32(2u * m + 1u, one));
        float L0 = -__logf(u0);
        float L1 = -__logf(u1);

        if (a * a * L1 >= bb * bb * L0)
            atomicAdd(&out[(size_t)i * KK + j], 0.125f);  // mean over B=8, exact
    }
}

// ---------------------------------------------------------------------------
// Launch
// ---------------------------------------------------------------------------
extern "C" void kernel_launch(void* const* d_in, const int* in_sizes, int n_in,
                              void* d_out, int out_size) {
    const float* amp = (const float*)d_in[0];
    const float* ph  = (const float*)d_in[1];
    const float* A   = (const float*)d_in[2];
    const float* wa  = (const float*)d_in[3];
    const float* wp  = (const float*)d_in[4];
    float* out = (float*)d_out;

    zero_out_kernel<<<(KK * KK) / TPB, TPB>>>(out);
    dist_sample_kernel<<<dim3(KK / ROWS, BK), TPB>>>(amp, ph, A, wa, wp, out, 1u);
}

// round 5
// speedup vs baseline: 2.8524x; 1.0528x over previous
#include <cuda_runtime.h>
#include <cstdint>
#include <math.h>
#include <float.h>

// Problem constants
#define BK  8
#define CK  32
#define KK  512
#define ROWS 8
#define TPB 512

// Scratch: bb = D - 0.99*Dmin per (b,i,j); a = 0.99*Dmin per (b,i)
__device__ float g_bb[BK * KK * KK];   // 8 MB
__device__ float g_a[BK * KK];         // 16 KB

// ---------------------------------------------------------------------------
// JAX threefry2x32 with key = (0, 42).  Random123 Threefry-2x32-20.
// All x0-side adds issued as IMAD with opaque `one` (fma pipe); rotates as
// single SHF via __funnelshift_l. Keeps the alu pipe for SHF/LOP3 only.
// ---------------------------------------------------------------------------
__device__ __forceinline__ void threefry2x32_k42(uint32_t x0, uint32_t x1,
                                                 uint32_t one,
                                                 uint32_t& o0, uint32_t& o1) {
    const uint32_t ks1 = 42u;
    const uint32_t ks2 = 0x1BD11BDAu ^ 42u;
#define MAD(dst, addend) \
    asm("mad.lo.s32 %0, %1, %2, %0;" : "+r"(dst) : "r"(addend), "r"(one))
#define TF_R(r) { MAD(x0, x1); x1 = __funnelshift_l(x1, x1, (r)); x1 ^= x0; }
    /* x0 += 0 */ x1 += ks1;
    TF_R(13) TF_R(15) TF_R(26) TF_R(6)
    { uint32_t k = ks1;      MAD(x0, k); } x1 += ks2 + 1u;
    TF_R(17) TF_R(29) TF_R(16) TF_R(24)
    { uint32_t k = ks2;      MAD(x0, k); } x1 += 0u + 2u;
    TF_R(13) TF_R(15) TF_R(26) TF_R(6)
    /* x0 += 0 */                          x1 += ks1 + 3u;
    TF_R(17) TF_R(29) TF_R(16) TF_R(24)
    { uint32_t k = ks1;      MAD(x0, k); } x1 += ks2 + 4u;
    TF_R(13) TF_R(15) TF_R(26) TF_R(6)
    { uint32_t k = ks2;      MAD(x0, k); } x1 += 0u + 5u;
#undef TF_R
#undef MAD
    o0 = x0; o1 = x1;
}

__device__ __forceinline__ uint32_t jax_random_bits32(uint32_t e, uint32_t one) {
    uint32_t a, b;
    threefry2x32_k42(0u, e, one, a, b);
    return a ^ b;
}

// jax.random.uniform bit->float, minval=1e-10, maxval=1.0 (f32)
__device__ __forceinline__ float jax_uniform(uint32_t bits) {
    float f = __uint_as_float((bits >> 9) | 0x3f800000u) - 1.0f;
    return fmaxf(1e-10f, f + 1e-10f);
}

// ---------------------------------------------------------------------------
// Kernel 1: distances + row minima  ->  g_bb, g_a
// ---------------------------------------------------------------------------
__global__ void __launch_bounds__(TPB, 2)
dist_kernel(const float* __restrict__ amp,
            const float* __restrict__ ph,
            const float* __restrict__ Amat,
            const float* __restrict__ wamp_p,
            const float* __restrict__ wph_p) {
    __shared__ float sQi[ROWS][CK];
    __shared__ float sSi[ROWS];
    __shared__ float sRed[16][ROWS];
    __shared__ float sC[ROWS];

    const int b    = blockIdx.y;
    const int j    = threadIdx.x;
    const int wid  = j >> 5;
    const int lane = j & 31;
    const int i0   = blockIdx.x * ROWS;

    const float wa = wamp_p[0];
    const float wp = wph_p[0];

    const float* ab = amp + (size_t)b * CK * KK;
    const float* pb = ph  + (size_t)b * CK * KK;

    float qj[CK];
    float Sj = 0.0f;
#pragma unroll
    for (int c = 0; c < CK; c++) {
        float v = wa * ab[c * KK + j] + wp * pb[c * KK + j];
        qj[c] = v;
        Sj = fmaf(v, v, Sj);
    }

    if (wid < ROWS) {
        const int i = i0 + wid;
        float v = wa * ab[lane * KK + i] + wp * pb[lane * KK + i];
        sQi[wid][lane] = v;
        float s = v * v;
#pragma unroll
        for (int o = 16; o; o >>= 1)
            s += __shfl_xor_sync(0xffffffffu, s, o);
        if (lane == 0) sSi[wid] = s;
    }

    const float dj   = Amat[(size_t)j * KK + j];
    const float djsq = dj * dj;
    __syncthreads();

    float D[ROWS];
#pragma unroll
    for (int r = 0; r < ROWS; r++) {
        float dot = 0.0f;
        const float2* q2 = (const float2*)sQi[r];
#pragma unroll
        for (int c2 = 0; c2 < CK / 2; c2++) {
            float2 qi = q2[c2];
            dot = fmaf(qi.x, qj[2 * c2], dot);
            dot = fmaf(qi.y, qj[2 * c2 + 1], dot);
        }
        float ss = fmaxf(fmaf(dot, -2.0f, sSi[r] + Sj), 0.0f);
        D[r] = (i0 + r == j) ? FLT_MAX : fmaf(ss, djsq, 1e-10f);
    }

#pragma unroll
    for (int r = 0; r < ROWS; r++) {
        float v = D[r];
#pragma unroll
        for (int o = 16; o; o >>= 1)
            v = fminf(v, __shfl_xor_sync(0xffffffffu, v, o));
        if (lane == 0) sRed[wid][r] = v;
    }
    __syncthreads();
    if (wid < ROWS) {
        float v = (lane < 16) ? sRed[lane][wid] : FLT_MAX;
#pragma unroll
        for (int o = 8; o; o >>= 1)
            v = fminf(v, __shfl_xor_sync(0xffffffffu, v, o));
        if (lane == 0) {
            sC[wid] = 0.99f * v;
            g_a[b * KK + i0 + wid] = 0.99f * v;
        }
    }
    __syncthreads();

#pragma unroll
    for (int r = 0; r < ROWS; r++) {
        const int i = i0 + r;
        float bb = (i == j) ? 0.01f : D[r] - sC[r];
        g_bb[((size_t)(b * KK + i) << 9) + j] = bb;
    }
}

// ---------------------------------------------------------------------------
// Kernel 2: gumbel-bernoulli decisions + mean over b  ->  out
// One thread per (i,j); block = 256 threads = half a row.
// ---------------------------------------------------------------------------
__global__ void __launch_bounds__(256, 6)
sample_kernel(float* __restrict__ out, uint32_t one) {
    const int i = blockIdx.x >> 1;
    const int j = ((blockIdx.x & 1) << 8) + threadIdx.x;
    const uint32_t m0 = ((uint32_t)i << 9) + (uint32_t)j;
    const bool diag = (i == j);

    float count = 0.0f;
#pragma unroll
    for (int b = 0; b < BK; b++) {
        float a, bb;
        bb = g_bb[((uint32_t)b << 18) + m0];
        a  = diag ? 0.99f : g_a[(b << 9) + i];

        uint32_t m = ((uint32_t)b << 18) + m0;
        float u0 = jax_uniform(jax_random_bits32(2u * m, one));
        float u1 = jax_uniform(jax_random_bits32(2u * m + 1u, one));
        float L0 = -__logf(u0);
        float L1 = -__logf(u1);

        if (a * a * L1 >= bb * bb * L0) count += 0.125f;
    }
    out[m0] = count;
}

// ---------------------------------------------------------------------------
// Launch
// ---------------------------------------------------------------------------
extern "C" void kernel_launch(void* const* d_in, const int* in_sizes, int n_in,
                              void* d_out, int out_size) {
    const float* amp = (const float*)d_in[0];
    const float* ph  = (const float*)d_in[1];
    const float* A   = (const float*)d_in[2];
    const float* wa  = (const float*)d_in[3];
    const float* wp  = (const float*)d_in[4];
    float* out = (float*)d_out;

    dist_kernel<<<dim3(KK / ROWS, BK), TPB>>>(amp, ph, A, wa, wp);
    sample_kernel<<<KK * 2, 256>>>(out, 1u);
}

// round 6
// speedup vs baseline: 3.1215x; 1.0943x over previous
#include <cuda_runtime.h>
#include <cstdint>
#include <math.h>
#include <float.h>

// Problem constants
#define BK  8
#define CK  32
#define KK  512
#define ROWS 16
#define TPB 512

// Scratch: raw D per (b,i,j); a = 0.99*Dmin per (b,i)
__device__ float g_D[BK * KK * KK];    // 8 MB
__device__ float g_a[BK * KK];         // 16 KB

// ---------------------------------------------------------------------------
// JAX threefry2x32 with key = (0, 42).  Random123 Threefry-2x32-20.
// Every add (round adds AND key injections) issued as IMAD with opaque `one`
// so they dispatch on the fma pipe; the alu pipe carries only SHF + LOP3.
// ---------------------------------------------------------------------------
__device__ __forceinline__ void threefry2x32_k42(uint32_t x0, uint32_t x1,
                                                 uint32_t one,
                                                 uint32_t& o0, uint32_t& o1) {
    const uint32_t ks1 = 42u;
    const uint32_t ks2 = 0x1BD11BDAu ^ 42u;
#define MADC(dst, cst) { uint32_t k_ = (cst); \
    asm("mad.lo.s32 %0, %1, %2, %0;" : "+r"(dst) : "r"(k_), "r"(one)); }
#define MAD(dst, addend) \
    asm("mad.lo.s32 %0, %1, %2, %0;" : "+r"(dst) : "r"(addend), "r"(one))
#define TF_R(r) { MAD(x0, x1); x1 = __funnelshift_l(x1, x1, (r)); x1 ^= x0; }
    /* x0 += 0 */ MADC(x1, ks1);
    TF_R(13) TF_R(15) TF_R(26) TF_R(6)
    MADC(x0, ks1); MADC(x1, ks2 + 1u);
    TF_R(17) TF_R(29) TF_R(16) TF_R(24)
    MADC(x0, ks2); MADC(x1, 2u);
    TF_R(13) TF_R(15) TF_R(26) TF_R(6)
    /* x0 += 0 */  MADC(x1, ks1 + 3u);
    TF_R(17) TF_R(29) TF_R(16) TF_R(24)
    MADC(x0, ks1); MADC(x1, ks2 + 4u);
    TF_R(13) TF_R(15) TF_R(26) TF_R(6)
    MADC(x0, ks2); MADC(x1, 5u);
#undef TF_R
#undef MAD
#undef MADC
    o0 = x0; o1 = x1;
}

__device__ __forceinline__ uint32_t jax_random_bits32(uint32_t e, uint32_t one) {
    uint32_t a, b;
    threefry2x32_k42(0u, e, one, a, b);
    return a ^ b;
}

// jax.random.uniform bit->float, minval=1e-10, maxval=1.0 (f32).
// f in [0,1) so max(1e-10, f+1e-10) == f+1e-10 exactly.
__device__ __forceinline__ float jax_uniform(uint32_t bits) {
    float f = __uint_as_float((bits >> 9) | 0x3f800000u) - 1.0f;
    return f + 1e-10f;
}

// ---------------------------------------------------------------------------
// Kernel 1: distances + row minima  ->  g_D (raw), g_a (0.99*Dmin)
// 256 blocks (single wave at 2 CTA/SM), 16 rows per block.
// ---------------------------------------------------------------------------
__global__ void __launch_bounds__(TPB, 2)
dist_kernel(const float* __restrict__ amp,
            const float* __restrict__ ph,
            const float* __restrict__ Amat,
            const float* __restrict__ wamp_p,
            const float* __restrict__ wph_p) {
    __shared__ float sQi[ROWS][CK];      // row vectors q_i
    __shared__ float sSi[ROWS];          // ||q_i||^2
    __shared__ float sRed[16][ROWS];     // per-warp row minima

    const int b    = blockIdx.y;
    const int j    = threadIdx.x;
    const int wid  = j >> 5;
    const int lane = j & 31;
    const int i0   = blockIdx.x * ROWS;

    const float wa = wamp_p[0];
    const float wp = wph_p[0];

    const float* ab = amp + (size_t)b * CK * KK;
    const float* pb = ph  + (size_t)b * CK * KK;

    // Per-thread column cache q_j[c] and its sum of squares
    float qj[CK];
    float Sj = 0.0f;
#pragma unroll
    for (int c = 0; c < CK; c++) {
        float v = wa * ab[c * KK + j] + wp * pb[c * KK + j];
        qj[c] = v;
        Sj = fmaf(v, v, Sj);
    }

    // Each of the 16 warps loads its row vector (lane = channel) + row SSQ
    {
        const int i = i0 + wid;
        float v = wa * ab[lane * KK + i] + wp * pb[lane * KK + i];
        sQi[wid][lane] = v;
        float s = v * v;
#pragma unroll
        for (int o = 16; o; o >>= 1)
            s += __shfl_xor_sync(0xffffffffu, s, o);
        if (lane == 0) sSi[wid] = s;
    }

    const float dj   = Amat[(size_t)j * KK + j];
    const float djsq = dj * dj;
    __syncthreads();

    // Phase A: D = djsq * ||q_i - q_j||^2 + 1e-10 (expanded); store raw D,
    // keep running per-warp row minimum.
#pragma unroll
    for (int r = 0; r < ROWS; r++) {
        float dot = 0.0f;
        const float2* q2 = (const float2*)sQi[r];
#pragma unroll
        for (int c2 = 0; c2 < CK / 2; c2++) {
            float2 qi = q2[c2];
            dot = fmaf(qi.x, qj[2 * c2], dot);
            dot = fmaf(qi.y, qj[2 * c2 + 1], dot);
        }
        float ss = fmaxf(fmaf(dot, -2.0f, sSi[r] + Sj), 0.0f);
        const int i = i0 + r;
        float D = (i == j) ? FLT_MAX : fmaf(ss, djsq, 1e-10f);
        g_D[((uint32_t)(b * KK + i) << 9) + (uint32_t)j] = D;

        float v = D;
#pragma unroll
        for (int o = 16; o; o >>= 1)
            v = fminf(v, __shfl_xor_sync(0xffffffffu, v, o));
        if (lane == 0) sRed[wid][r] = v;
    }
    __syncthreads();

    // Phase B: combine 16 warp-partials per row; warp w handles row w.
    {
        float v = (lane < 16) ? sRed[lane][wid] : FLT_MAX;
#pragma unroll
        for (int o = 8; o; o >>= 1)
            v = fminf(v, __shfl_xor_sync(0xffffffffu, v, o));
        if (lane == 0) g_a[b * KK + i0 + wid] = 0.99f * v;
    }
}

// ---------------------------------------------------------------------------
// Kernel 2: gumbel-bernoulli decisions + mean over b  ->  out
// One thread per (i,j); small blocks stream to minimize the tail.
// ---------------------------------------------------------------------------
__global__ void __launch_bounds__(128, 12)
sample_kernel(float* __restrict__ out, uint32_t one) {
    const uint32_t m0 = blockIdx.x * 128u + threadIdx.x;   // (i<<9) + j
    const int i = (int)(m0 >> 9);
    const int j = (int)(m0 & 511u);
    const bool diag = (i == j);

    float count = 0.0f;
#pragma unroll
    for (int b = 0; b < BK; b++) {
        float D = g_D[((uint32_t)b << 18) + m0];
        float a = diag ? 0.99f : g_a[(b << 9) + i];
        float bb = diag ? 0.01f : D - a;

        uint32_t m = ((uint32_t)b << 18) + m0;
        float u0 = jax_uniform(jax_random_bits32(2u * m, one));
        float u1 = jax_uniform(jax_random_bits32(2u * m + 1u, one));
        float L0 = -__logf(u0);
        float L1 = -__logf(u1);

        if (a * a * L1 >= bb * bb * L0) count += 0.125f;
    }
    out[m0] = count;
}

// ---------------------------------------------------------------------------
// Launch
// ---------------------------------------------------------------------------
extern "C" void kernel_launch(void* const* d_in, const int* in_sizes, int n_in,
                              void* d_out, int out_size) {
    const float* amp = (const float*)d_in[0];
    const float* ph  = (const float*)d_in[1];
    const float* A   = (const float*)d_in[2];
    const float* wa  = (const float*)d_in[3];
    const float* wp  = (const float*)d_in[4];
    float* out = (float*)d_out;

    dist_kernel<<<dim3(KK / ROWS, BK), TPB>>>(amp, ph, A, wa, wp);
    sample_kernel<<<(KK * KK) / 128, 128>>>(out, 1u);
}